// round 6
// baseline (speedup 1.0000x reference)
#include <cuda_runtime.h>

#define N_MODES   16
#define N_LAYERS  6
#define LIN_P     528           // 4*120 + 3*16
#define OUT_COLS  10
#define TPB       128
#define SPT       2             // samples per thread

typedef unsigned long long ull;

// ---------------------------------------------------------------------------
// Device-global scratch (allocation-free per harness rules)
// ---------------------------------------------------------------------------
__device__ float g_S[12][32][32];            // real symplectic mats
__device__ float g_W[N_LAYERS][32][32];      // composed weights, TRANSPOSED: [l][in][out]
__device__ float g_Wc[32][20];               // last layer compact: [in][x0..x9,p0..p9]
__device__ float g_d[N_LAYERS][32];          // displacements
__device__ float g_dc[20];                   // last-layer displacement, compact

// ---------------------------------------------------------------------------
// f32x2 packed-FMA helpers (Blackwell FFMA2)
// ---------------------------------------------------------------------------
__device__ __forceinline__ ull ffma2(ull a, ull b, ull c) {
    ull d;
    asm("fma.rn.f32x2 %0, %1, %2, %3;" : "=l"(d) : "l"(a), "l"(b), "l"(c));
    return d;
}
__device__ __forceinline__ ull dup_f32(float x) {
    ull d;
    unsigned int u = __float_as_uint(x);
    asm("mov.b64 %0, {%1, %1};" : "=l"(d) : "r"(u));
    return d;
}
__device__ __forceinline__ ull pack2(float x, float y) {
    ull d;
    asm("mov.b64 %0, {%1, %2};" : "=l"(d)
        : "r"(__float_as_uint(x)), "r"(__float_as_uint(y)));
    return d;
}
__device__ __forceinline__ void unpack2(ull a, float& x, float& y) {
    unsigned int lo, hi;
    asm("mov.b64 {%0, %1}, %2;" : "=r"(lo), "=r"(hi) : "l"(a));
    x = __uint_as_float(lo);
    y = __uint_as_float(hi);
}

// ---------------------------------------------------------------------------
// Setup kernel: build per-layer 32x32 affine maps from linear_params.
// One block, 1024 threads. MUFU intrinsics: angles/squeezes are O(1e-3);
// accumulated weight error ~1e-5, negligible vs the 1e-3 test tolerance.
// ---------------------------------------------------------------------------
__global__ void setup_kernel(const float* __restrict__ lin) {
    int tid = threadIdx.x;
    __shared__ float s_scale[N_LAYERS][32];

    if (tid < 192) {
        // ---- interferometer scan: 12 groups x 16 threads, one column each ----
        int g   = tid >> 4;          // 0..11 = 2*layer + which
        int col = tid & 15;
        int l   = g >> 1;
        int w   = g & 1;
        const float* lp = lin + l * LIN_P;
        const float* th = lp + (w ? 256 : 0);
        const float* ph = lp + (w ? 376 : 120);

        float ur[16], ui[16];
        #pragma unroll
        for (int m = 0; m < 16; ++m) { ur[m] = (m == col) ? 1.f : 0.f; ui[m] = 0.f; }

        int k = 0;
        #pragma unroll
        for (int i = 0; i < 16; ++i) {
            #pragma unroll
            for (int j = i + 1; j < 16; ++j) {
                float t = th[k], p = ph[k];
                float s, c, sp, cp;
                __sincosf(t, &s, &c);
                __sincosf(p, &sp, &cp);
                float br = cp * s, bi = sp * s;      // e*s = (br, bi)
                float air = ur[i], aii = ui[i];
                float ajr = ur[j], aji = ui[j];
                // U[i] = c*ri - conj(e)*s*rj
                ur[i] = c * air - (br * ajr + bi * aji);
                ui[i] = c * aii - (br * aji - bi * ajr);
                // U[j] = e*s*ri + c*rj
                ur[j] = (br * air - bi * aii) + c * ajr;
                ui[j] = (br * aii + bi * air) + c * aji;
                ++k;
            }
        }
        // expand to real symplectic [[Re, -Im], [Im, Re]]
        #pragma unroll
        for (int m = 0; m < 16; ++m) {
            g_S[g][m][col]           =  ur[m];
            g_S[g][m][col + 16]      = -ui[m];
            g_S[g][m + 16][col]      =  ui[m];
            g_S[g][m + 16][col + 16] =  ur[m];
        }
    }

    if (tid < 192) {
        // ---- squeezing scales + displacement ----
        int l = tid >> 5, kk = tid & 31;
        const float* lp = lin + l * LIN_P;
        float r = lp[240 + (kk & 15)];
        s_scale[l][kk] = __expf(kk < 16 ? -r : r);
        g_d[l][kk] = lp[496 + kk];
    }
    __syncthreads();

    // ---- compose W[l][i][o] = sum_k S2[o][k]*scale[k]*S1[k][i] ----
    {
        int i = tid >> 5, o = tid & 31;
        #pragma unroll 1
        for (int l = 0; l < N_LAYERS; ++l) {
            float acc = 0.f;
            #pragma unroll
            for (int k = 0; k < 32; ++k)
                acc += g_S[2 * l + 1][o][k] * s_scale[l][k] * g_S[2 * l][k][i];
            g_W[l][i][o] = acc;
        }
    }
    __syncthreads();

    // ---- compact last layer: keep only outputs {0..9, 16..25} ----
    if (tid < 640) {
        int i = tid / 20, j = tid % 20;
        g_Wc[i][j] = g_W[N_LAYERS - 1][i][j < 10 ? j : j + 6];
    }
    if (tid < 20) g_dc[tid] = g_d[N_LAYERS - 1][tid < 10 ? tid : tid + 6];
}

// ---------------------------------------------------------------------------
// Affine layer on TWO samples: one LDS.128 of weights feeds 4 FFMA2s.
// W laid out [in][out], STRIDE floats per row; NP output f32x2 pairs.
// ---------------------------------------------------------------------------
template<int NIN, int NP, int STRIDE>
__device__ __forceinline__ void linear2(float* va, float* vb,
                                        const float* __restrict__ W,
                                        const float* __restrict__ dv) {
    ull a0[NP], a1[NP];
    #pragma unroll
    for (int k = 0; k < NP; ++k) {
        ull t = pack2(dv[2 * k], dv[2 * k + 1]);
        a0[k] = t; a1[k] = t;
    }
    #pragma unroll
    for (int i = 0; i < NIN; ++i) {
        ull da = dup_f32(va[i]);
        ull db = dup_f32(vb[i]);
        const ulonglong2* wr = reinterpret_cast<const ulonglong2*>(W + i * STRIDE);
        #pragma unroll
        for (int q = 0; q < NP / 2; ++q) {
            ulonglong2 w2 = wr[q];                 // 4 weights = 2 output pairs
            a0[2 * q]     = ffma2(da, w2.x, a0[2 * q]);
            a0[2 * q + 1] = ffma2(da, w2.y, a0[2 * q + 1]);
            a1[2 * q]     = ffma2(db, w2.x, a1[2 * q]);
            a1[2 * q + 1] = ffma2(db, w2.y, a1[2 * q + 1]);
        }
    }
    #pragma unroll
    for (int k = 0; k < NP; ++k) {
        unpack2(a0[k], va[2 * k], va[2 * k + 1]);
        unpack2(a1[k], vb[2 * k], vb[2 * k + 1]);
    }
}

__device__ __forceinline__ void kerr16(float* v, const float* __restrict__ kp) {
    #pragma unroll
    for (int m = 0; m < 16; ++m) {
        float x = v[m], p = v[m + 16];
        float ang = kp[m] * (x * x + p * p);
        float s, c;
        __sincosf(ang, &s, &c);
        v[m]      = fmaf(c, x,  s * p);
        v[m + 16] = fmaf(c, p, -s * x);
    }
}

// ---------------------------------------------------------------------------
// Main kernel: 2 samples per thread; state in registers; weights in SMEM.
// ---------------------------------------------------------------------------
__global__ void __launch_bounds__(TPB) qnet_main(
    const float* __restrict__ batch,
    const float* __restrict__ act_p,      // (5, 16)
    const float* __restrict__ last_act,   // (16,)
    float* __restrict__ out,
    int n_samples)
{
    __shared__ __align__(16) float sW[N_LAYERS - 1][32][32];  // layers 0..4: 20 KB
    __shared__ __align__(16) float sWc[32][20];               // layer 5 compact
    __shared__ float sd[N_LAYERS - 1][32];
    __shared__ float sdc[20];
    __shared__ float sk[N_LAYERS][16];

    int tid = threadIdx.x;
    {
        const float4* src = reinterpret_cast<const float4*>(g_W);
        float4* dst = reinterpret_cast<float4*>(&sW[0][0][0]);
        for (int idx = tid; idx < (N_LAYERS - 1) * 32 * 32 / 4; idx += TPB) dst[idx] = src[idx];
        const float4* srcc = reinterpret_cast<const float4*>(&g_Wc[0][0]);
        float4* dstc = reinterpret_cast<float4*>(&sWc[0][0]);
        for (int idx = tid; idx < 32 * 20 / 4; idx += TPB) dstc[idx] = srcc[idx];
        // strided loop: (N_LAYERS-1)*32 = 160 > TPB, a plain conditional here
        // silently leaves sd[4][...] uninitialized (the R2 bug)
        for (int idx = tid; idx < (N_LAYERS - 1) * 32; idx += TPB)
            (&sd[0][0])[idx] = (&g_d[0][0])[idx];
        if (tid < 20) sdc[tid] = g_dc[tid];
        if (tid < 80)       (&sk[0][0])[tid] = act_p[tid];
        else if (tid < 96)  (&sk[0][0])[tid] = last_act[tid - 80];
    }
    __syncthreads();

    int sa = blockIdx.x * (TPB * SPT) + tid;          // sample A
    int sb = sa + TPB;                                // sample B (coalesced)

    float va[32], vb[32];
    {
        const float4* ba = reinterpret_cast<const float4*>(batch + (size_t)sa * 16);
        const float4* bb = reinterpret_cast<const float4*>(batch + (size_t)sb * 16);
        #pragma unroll
        for (int q = 0; q < 4; ++q) {
            float4 t = (sa < n_samples) ? ba[q] : make_float4(0.f, 0.f, 0.f, 0.f);
            va[4 * q] = t.x; va[4 * q + 1] = t.y; va[4 * q + 2] = t.z; va[4 * q + 3] = t.w;
            float4 u = (sb < n_samples) ? bb[q] : make_float4(0.f, 0.f, 0.f, 0.f);
            vb[4 * q] = u.x; vb[4 * q + 1] = u.y; vb[4 * q + 2] = u.z; vb[4 * q + 3] = u.w;
        }
        #pragma unroll
        for (int m = 16; m < 32; ++m) { va[m] = 0.f; vb[m] = 0.f; }
    }

    // layer 0: inputs 16..31 are zero -> only 16 i-steps
    linear2<16, 16, 32>(va, vb, &sW[0][0][0], &sd[0][0]);
    kerr16(va, &sk[0][0]);
    kerr16(vb, &sk[0][0]);

    #pragma unroll 1
    for (int l = 1; l < N_LAYERS - 1; ++l) {
        linear2<32, 16, 32>(va, vb, &sW[l][0][0], &sd[l][0]);
        kerr16(va, &sk[l][0]);
        kerr16(vb, &sk[l][0]);
    }

    // last layer: only outputs x0..x9 (cols 0..9) and p0..p9 (cols 10..19)
    linear2<32, 10, 20>(va, vb, &sWc[0][0], sdc);

    float oa[OUT_COLS], ob[OUT_COLS];
    #pragma unroll
    for (int m = 0; m < OUT_COLS; ++m) {
        float ka = sk[N_LAYERS - 1][m];
        float x = va[m], p = va[10 + m];
        float ang = ka * (x * x + p * p);
        float s, c;
        __sincosf(ang, &s, &c);
        oa[m] = fmaf(c, x, s * p);
        x = vb[m]; p = vb[10 + m];
        ang = ka * (x * x + p * p);
        __sincosf(ang, &s, &c);
        ob[m] = fmaf(c, x, s * p);
    }

    if (sa < n_samples) {
        float2* orow = reinterpret_cast<float2*>(out + (size_t)sa * OUT_COLS);
        #pragma unroll
        for (int m = 0; m < 5; ++m) orow[m] = make_float2(oa[2 * m], oa[2 * m + 1]);
    }
    if (sb < n_samples) {
        float2* orow = reinterpret_cast<float2*>(out + (size_t)sb * OUT_COLS);
        #pragma unroll
        for (int m = 0; m < 5; ++m) orow[m] = make_float2(ob[2 * m], ob[2 * m + 1]);
    }
}

// ---------------------------------------------------------------------------
extern "C" void kernel_launch(void* const* d_in, const int* in_sizes, int n_in,
                              void* d_out, int out_size) {
    const float* batch    = (const float*)d_in[0];   // (B, 16)
    const float* lin      = (const float*)d_in[1];   // (6, 528)
    const float* act_p    = (const float*)d_in[2];   // (5, 16)
    const float* last_act = (const float*)d_in[3];   // (16,)
    float* out = (float*)d_out;

    int n_samples = in_sizes[0] / N_MODES;
    int blocks = (n_samples + TPB * SPT - 1) / (TPB * SPT);

    setup_kernel<<<1, 1024>>>(lin);
    qnet_main<<<blocks, TPB>>>(batch, act_p, last_act, out, n_samples);
}

// round 7
// speedup vs baseline: 1.5741x; 1.5741x over previous
#include <cuda_runtime.h>

#define N_MODES   16
#define N_LAYERS  6
#define LIN_P     528           // 4*120 + 3*16
#define OUT_COLS  10
#define TPB       128
#define SPT       3             // samples per thread

typedef unsigned long long ull;

// ---------------------------------------------------------------------------
// Device-global scratch (allocation-free per harness rules)
// ---------------------------------------------------------------------------
__device__ float g_S[12][32][32];            // real symplectic mats
__device__ float g_W[N_LAYERS][32][32];      // composed weights, TRANSPOSED: [l][in][out]
__device__ float g_Wc[32][20];               // last layer compact: [in][x0..x9,p0..p9]
__device__ float g_d[N_LAYERS][32];          // displacements
__device__ float g_dc[20];                   // last-layer displacement, compact

// ---------------------------------------------------------------------------
// f32x2 packed-FMA helpers (Blackwell FFMA2)
// ---------------------------------------------------------------------------
__device__ __forceinline__ ull ffma2(ull a, ull b, ull c) {
    ull d;
    asm("fma.rn.f32x2 %0, %1, %2, %3;" : "=l"(d) : "l"(a), "l"(b), "l"(c));
    return d;
}
__device__ __forceinline__ ull dup_f32(float x) {
    ull d;
    unsigned int u = __float_as_uint(x);
    asm("mov.b64 %0, {%1, %1};" : "=l"(d) : "r"(u));
    return d;
}
__device__ __forceinline__ ull pack2(float x, float y) {
    ull d;
    asm("mov.b64 %0, {%1, %2};" : "=l"(d)
        : "r"(__float_as_uint(x)), "r"(__float_as_uint(y)));
    return d;
}
__device__ __forceinline__ void unpack2(ull a, float& x, float& y) {
    unsigned int lo, hi;
    asm("mov.b64 {%0, %1}, %2;" : "=r"(lo), "=r"(hi) : "l"(a));
    x = __uint_as_float(lo);
    y = __uint_as_float(hi);
}

// ---------------------------------------------------------------------------
// Setup kernel: build per-layer 32x32 affine maps from linear_params.
// One block, 1024 threads.
// Compose phase stages S1/S2 in SMEM: coalesced GMEM loads, padded rows for
// conflict-free LDS (the R6 version did 32-line uncoalesced LDGs -> ~108us).
// ---------------------------------------------------------------------------
__global__ void setup_kernel(const float* __restrict__ lin) {
    int tid = threadIdx.x;
    __shared__ float s_scale[N_LAYERS][32];
    __shared__ float sS1[32][32];     // S1[k][i]   (broadcast reads)
    __shared__ float sS2[32][33];     // S2[o][k]   padded: lane-varying row reads

    if (tid < 192) {
        // ---- interferometer scan: 12 groups x 16 threads, one column each ----
        int g   = tid >> 4;          // 0..11 = 2*layer + which
        int col = tid & 15;
        int l   = g >> 1;
        int w   = g & 1;
        const float* lp = lin + l * LIN_P;
        const float* th = lp + (w ? 256 : 0);
        const float* ph = lp + (w ? 376 : 120);

        float ur[16], ui[16];
        #pragma unroll
        for (int m = 0; m < 16; ++m) { ur[m] = (m == col) ? 1.f : 0.f; ui[m] = 0.f; }

        int k = 0;
        #pragma unroll
        for (int i = 0; i < 16; ++i) {
            #pragma unroll
            for (int j = i + 1; j < 16; ++j) {
                float t = th[k], p = ph[k];
                float s, c, sp, cp;
                __sincosf(t, &s, &c);
                __sincosf(p, &sp, &cp);
                float br = cp * s, bi = sp * s;      // e*s = (br, bi)
                float air = ur[i], aii = ui[i];
                float ajr = ur[j], aji = ui[j];
                ur[i] = c * air - (br * ajr + bi * aji);
                ui[i] = c * aii - (br * aji - bi * ajr);
                ur[j] = (br * air - bi * aii) + c * ajr;
                ui[j] = (br * aii + bi * air) + c * aji;
                ++k;
            }
        }
        // expand to real symplectic [[Re, -Im], [Im, Re]]
        #pragma unroll
        for (int m = 0; m < 16; ++m) {
            g_S[g][m][col]           =  ur[m];
            g_S[g][m][col + 16]      = -ui[m];
            g_S[g][m + 16][col]      =  ui[m];
            g_S[g][m + 16][col + 16] =  ur[m];
        }
    }

    if (tid < 192) {
        // ---- squeezing scales + displacement ----
        int l = tid >> 5, kk = tid & 31;
        const float* lp = lin + l * LIN_P;
        float r = lp[240 + (kk & 15)];
        s_scale[l][kk] = __expf(kk < 16 ? -r : r);
        g_d[l][kk] = lp[496 + kk];
    }
    __syncthreads();

    // ---- compose W[l][i][o] = sum_k S2[o][k]*scale[k]*S1[k][i] ----
    // mapping: i = warp (uniform), o = lane.
    //   sS2[o][k]: lane-varying row, padded stride 33 -> conflict-free
    //   sS1[k][i], s_scale[l][k]: warp-uniform -> broadcast
    //   g_W[l][i][o] store: lane-consecutive -> coalesced
    {
        int r = tid >> 5, c = tid & 31;
        #pragma unroll 1
        for (int l = 0; l < N_LAYERS; ++l) {
            sS1[r][c] = g_S[2 * l][r][c];          // coalesced 128B rows
            sS2[r][c] = g_S[2 * l + 1][r][c];
            __syncthreads();
            int i = r, o = c;
            float acc = 0.f;
            #pragma unroll
            for (int k = 0; k < 32; ++k)
                acc += sS2[o][k] * (s_scale[l][k] * sS1[k][i]);
            g_W[l][i][o] = acc;
            __syncthreads();
        }
    }

    // ---- compact last layer: keep only outputs {0..9, 16..25} ----
    if (tid < 640) {
        int i = tid / 20, j = tid % 20;
        g_Wc[i][j] = g_W[N_LAYERS - 1][i][j < 10 ? j : j + 6];
    }
    if (tid < 20) g_dc[tid] = g_d[N_LAYERS - 1][tid < 10 ? tid : tid + 6];
}

// ---------------------------------------------------------------------------
// Affine layer on NS samples: one LDS.128 of weights feeds 2*NS FFMA2s.
// W laid out [in][out], STRIDE floats per row; NP output f32x2 pairs.
// ---------------------------------------------------------------------------
template<int NS, int NIN, int NP, int STRIDE>
__device__ __forceinline__ void linearN(float (&v)[NS][32],
                                        const float* __restrict__ W,
                                        const float* __restrict__ dv) {
    ull acc[NS][NP];
    #pragma unroll
    for (int k = 0; k < NP; ++k) {
        ull t = pack2(dv[2 * k], dv[2 * k + 1]);
        #pragma unroll
        for (int s = 0; s < NS; ++s) acc[s][k] = t;
    }
    #pragma unroll
    for (int i = 0; i < NIN; ++i) {
        ull dm[NS];
        #pragma unroll
        for (int s = 0; s < NS; ++s) dm[s] = dup_f32(v[s][i]);
        const ulonglong2* wr = reinterpret_cast<const ulonglong2*>(W + i * STRIDE);
        #pragma unroll
        for (int q = 0; q < NP / 2; ++q) {
            ulonglong2 w2 = wr[q];                 // 4 weights = 2 output pairs
            #pragma unroll
            for (int s = 0; s < NS; ++s) {
                acc[s][2 * q]     = ffma2(dm[s], w2.x, acc[s][2 * q]);
                acc[s][2 * q + 1] = ffma2(dm[s], w2.y, acc[s][2 * q + 1]);
            }
        }
    }
    #pragma unroll
    for (int k = 0; k < NP; ++k)
        #pragma unroll
        for (int s = 0; s < NS; ++s)
            unpack2(acc[s][k], v[s][2 * k], v[s][2 * k + 1]);
}

__device__ __forceinline__ void kerr16(float* v, const float* __restrict__ kp) {
    #pragma unroll
    for (int m = 0; m < 16; ++m) {
        float x = v[m], p = v[m + 16];
        float ang = kp[m] * (x * x + p * p);
        float s, c;
        __sincosf(ang, &s, &c);
        v[m]      = fmaf(c, x,  s * p);
        v[m + 16] = fmaf(c, p, -s * x);
    }
}

// ---------------------------------------------------------------------------
// Main kernel: SPT samples per thread; state in registers; weights in SMEM.
// ---------------------------------------------------------------------------
__global__ void __launch_bounds__(TPB) qnet_main(
    const float* __restrict__ batch,
    const float* __restrict__ act_p,      // (5, 16)
    const float* __restrict__ last_act,   // (16,)
    float* __restrict__ out,
    int n_samples)
{
    __shared__ __align__(16) float sW[N_LAYERS - 1][32][32];  // layers 0..4: 20 KB
    __shared__ __align__(16) float sWc[32][20];               // layer 5 compact
    __shared__ float sd[N_LAYERS - 1][32];
    __shared__ float sdc[20];
    __shared__ float sk[N_LAYERS][16];

    int tid = threadIdx.x;
    {
        const float4* src = reinterpret_cast<const float4*>(g_W);
        float4* dst = reinterpret_cast<float4*>(&sW[0][0][0]);
        for (int idx = tid; idx < (N_LAYERS - 1) * 32 * 32 / 4; idx += TPB) dst[idx] = src[idx];
        const float4* srcc = reinterpret_cast<const float4*>(&g_Wc[0][0]);
        float4* dstc = reinterpret_cast<float4*>(&sWc[0][0]);
        for (int idx = tid; idx < 32 * 20 / 4; idx += TPB) dstc[idx] = srcc[idx];
        for (int idx = tid; idx < (N_LAYERS - 1) * 32; idx += TPB)
            (&sd[0][0])[idx] = (&g_d[0][0])[idx];
        if (tid < 20) sdc[tid] = g_dc[tid];
        if (tid < 80)       (&sk[0][0])[tid] = act_p[tid];
        else if (tid < 96)  (&sk[0][0])[tid] = last_act[tid - 80];
    }
    __syncthreads();

    int s0 = blockIdx.x * (TPB * SPT) + tid;          // sample of slot 0

    float v[SPT][32];
    #pragma unroll
    for (int s = 0; s < SPT; ++s) {
        int sid = s0 + s * TPB;                       // coalesced within warp
        const float4* br = reinterpret_cast<const float4*>(batch + (size_t)sid * 16);
        #pragma unroll
        for (int q = 0; q < 4; ++q) {
            float4 t = (sid < n_samples) ? br[q] : make_float4(0.f, 0.f, 0.f, 0.f);
            v[s][4 * q] = t.x; v[s][4 * q + 1] = t.y;
            v[s][4 * q + 2] = t.z; v[s][4 * q + 3] = t.w;
        }
        #pragma unroll
        for (int m = 16; m < 32; ++m) v[s][m] = 0.f;
    }

    // layer 0: inputs 16..31 are zero -> only 16 i-steps
    linearN<SPT, 16, 16, 32>(v, &sW[0][0][0], &sd[0][0]);
    #pragma unroll
    for (int s = 0; s < SPT; ++s) kerr16(v[s], &sk[0][0]);

    #pragma unroll 1
    for (int l = 1; l < N_LAYERS - 1; ++l) {
        linearN<SPT, 32, 16, 32>(v, &sW[l][0][0], &sd[l][0]);
        #pragma unroll
        for (int s = 0; s < SPT; ++s) kerr16(v[s], &sk[l][0]);
    }

    // last layer: only outputs x0..x9 (cols 0..9) and p0..p9 (cols 10..19)
    linearN<SPT, 32, 10, 20>(v, &sWc[0][0], sdc);

    #pragma unroll
    for (int s = 0; s < SPT; ++s) {
        int sid = s0 + s * TPB;
        float o10[OUT_COLS];
        #pragma unroll
        for (int m = 0; m < OUT_COLS; ++m) {
            float ka = sk[N_LAYERS - 1][m];
            float x = v[s][m], p = v[s][10 + m];
            float ang = ka * (x * x + p * p);
            float sn, cs;
            __sincosf(ang, &sn, &cs);
            o10[m] = fmaf(cs, x, sn * p);
        }
        if (sid < n_samples) {
            float2* orow = reinterpret_cast<float2*>(out + (size_t)sid * OUT_COLS);
            #pragma unroll
            for (int m = 0; m < 5; ++m) orow[m] = make_float2(o10[2 * m], o10[2 * m + 1]);
        }
    }
}

// ---------------------------------------------------------------------------
extern "C" void kernel_launch(void* const* d_in, const int* in_sizes, int n_in,
                              void* d_out, int out_size) {
    const float* batch    = (const float*)d_in[0];   // (B, 16)
    const float* lin      = (const float*)d_in[1];   // (6, 528)
    const float* act_p    = (const float*)d_in[2];   // (5, 16)
    const float* last_act = (const float*)d_in[3];   // (16,)
    float* out = (float*)d_out;

    int n_samples = in_sizes[0] / N_MODES;
    int blocks = (n_samples + TPB * SPT - 1) / (TPB * SPT);

    setup_kernel<<<1, 1024>>>(lin);
    qnet_main<<<blocks, TPB>>>(batch, act_p, last_act, out, n_samples);
}

// round 8
// speedup vs baseline: 1.7161x; 1.0902x over previous
#include <cuda_runtime.h>

#define N_MODES   16
#define N_LAYERS  6
#define LIN_P     528           // 4*120 + 3*16
#define OUT_COLS  10
#define TPB       128
#define SPT       2             // samples per thread

typedef unsigned long long ull;

// ---------------------------------------------------------------------------
// Device-global scratch (allocation-free per harness rules)
// ---------------------------------------------------------------------------
__device__ float g_S[12][32][32];            // real symplectic mats
__device__ float g_W[N_LAYERS][32][32];      // composed weights, TRANSPOSED: [l][in][out]
__device__ float g_Wc[32][20];               // last layer compact: [in][x0..x9,p0..p9]
__device__ float g_d[N_LAYERS][32];          // displacements
__device__ float g_dc[20];                   // last-layer displacement, compact

// ---------------------------------------------------------------------------
// f32x2 packed-FMA helpers (Blackwell FFMA2)
// ---------------------------------------------------------------------------
__device__ __forceinline__ ull ffma2(ull a, ull b, ull c) {
    ull d;
    asm("fma.rn.f32x2 %0, %1, %2, %3;" : "=l"(d) : "l"(a), "l"(b), "l"(c));
    return d;
}
__device__ __forceinline__ ull dup_f32(float x) {
    ull d;
    unsigned int u = __float_as_uint(x);
    asm("mov.b64 %0, {%1, %1};" : "=l"(d) : "r"(u));
    return d;
}
__device__ __forceinline__ ull pack2(float x, float y) {
    ull d;
    asm("mov.b64 %0, {%1, %2};" : "=l"(d)
        : "r"(__float_as_uint(x)), "r"(__float_as_uint(y)));
    return d;
}
__device__ __forceinline__ void unpack2(ull a, float& x, float& y) {
    unsigned int lo, hi;
    asm("mov.b64 {%0, %1}, %2;" : "=r"(lo), "=r"(hi) : "l"(a));
    x = __uint_as_float(lo);
    y = __uint_as_float(hi);
}

// ---------------------------------------------------------------------------
// Setup kernel: build per-layer 32x32 affine maps from linear_params.
// One block, 1024 threads. Compose phase stages S1/S2 in SMEM (coalesced
// GMEM, padded rows for conflict-free LDS) -- ~9us measured.
// ---------------------------------------------------------------------------
__global__ void setup_kernel(const float* __restrict__ lin) {
    int tid = threadIdx.x;
    __shared__ float s_scale[N_LAYERS][32];
    __shared__ float sS1[32][32];     // S1[k][i]   (broadcast reads)
    __shared__ float sS2[32][33];     // S2[o][k]   padded: lane-varying row reads

    if (tid < 192) {
        // ---- interferometer scan: 12 groups x 16 threads, one column each ----
        int g   = tid >> 4;          // 0..11 = 2*layer + which
        int col = tid & 15;
        int l   = g >> 1;
        int w   = g & 1;
        const float* lp = lin + l * LIN_P;
        const float* th = lp + (w ? 256 : 0);
        const float* ph = lp + (w ? 376 : 120);

        float ur[16], ui[16];
        #pragma unroll
        for (int m = 0; m < 16; ++m) { ur[m] = (m == col) ? 1.f : 0.f; ui[m] = 0.f; }

        int k = 0;
        #pragma unroll
        for (int i = 0; i < 16; ++i) {
            #pragma unroll
            for (int j = i + 1; j < 16; ++j) {
                float t = th[k], p = ph[k];
                float s, c, sp, cp;
                __sincosf(t, &s, &c);
                __sincosf(p, &sp, &cp);
                float br = cp * s, bi = sp * s;      // e*s = (br, bi)
                float air = ur[i], aii = ui[i];
                float ajr = ur[j], aji = ui[j];
                ur[i] = c * air - (br * ajr + bi * aji);
                ui[i] = c * aii - (br * aji - bi * ajr);
                ur[j] = (br * air - bi * aii) + c * ajr;
                ui[j] = (br * aii + bi * air) + c * aji;
                ++k;
            }
        }
        // expand to real symplectic [[Re, -Im], [Im, Re]]
        #pragma unroll
        for (int m = 0; m < 16; ++m) {
            g_S[g][m][col]           =  ur[m];
            g_S[g][m][col + 16]      = -ui[m];
            g_S[g][m + 16][col]      =  ui[m];
            g_S[g][m + 16][col + 16] =  ur[m];
        }
    }

    if (tid < 192) {
        // ---- squeezing scales + displacement ----
        int l = tid >> 5, kk = tid & 31;
        const float* lp = lin + l * LIN_P;
        float r = lp[240 + (kk & 15)];
        s_scale[l][kk] = __expf(kk < 16 ? -r : r);
        g_d[l][kk] = lp[496 + kk];
    }
    __syncthreads();

    // ---- compose W[l][i][o] = sum_k S2[o][k]*scale[k]*S1[k][i] ----
    {
        int r = tid >> 5, c = tid & 31;
        #pragma unroll 1
        for (int l = 0; l < N_LAYERS; ++l) {
            sS1[r][c] = g_S[2 * l][r][c];          // coalesced 128B rows
            sS2[r][c] = g_S[2 * l + 1][r][c];
            __syncthreads();
            int i = r, o = c;
            float acc = 0.f;
            #pragma unroll
            for (int k = 0; k < 32; ++k)
                acc += sS2[o][k] * (s_scale[l][k] * sS1[k][i]);
            g_W[l][i][o] = acc;
            __syncthreads();
        }
    }

    // ---- compact last layer: keep only outputs {0..9, 16..25} ----
    if (tid < 640) {
        int i = tid / 20, j = tid % 20;
        g_Wc[i][j] = g_W[N_LAYERS - 1][i][j < 10 ? j : j + 6];
    }
    if (tid < 20) g_dc[tid] = g_d[N_LAYERS - 1][tid < 10 ? tid : tid + 6];
}

// ---------------------------------------------------------------------------
// Affine layer on NS samples: one LDS.128 of weights feeds 2*NS FFMA2s.
// W laid out [in][out], STRIDE floats per row; NP output f32x2 pairs.
// ---------------------------------------------------------------------------
template<int NS, int NIN, int NP, int STRIDE>
__device__ __forceinline__ void linearN(float (&v)[NS][32],
                                        const float* __restrict__ W,
                                        const float* __restrict__ dv) {
    ull acc[NS][NP];
    #pragma unroll
    for (int k = 0; k < NP; ++k) {
        ull t = pack2(dv[2 * k], dv[2 * k + 1]);
        #pragma unroll
        for (int s = 0; s < NS; ++s) acc[s][k] = t;
    }
    #pragma unroll
    for (int i = 0; i < NIN; ++i) {
        ull dm[NS];
        #pragma unroll
        for (int s = 0; s < NS; ++s) dm[s] = dup_f32(v[s][i]);
        const ulonglong2* wr = reinterpret_cast<const ulonglong2*>(W + i * STRIDE);
        #pragma unroll
        for (int q = 0; q < NP / 2; ++q) {
            ulonglong2 w2 = wr[q];                 // 4 weights = 2 output pairs
            #pragma unroll
            for (int s = 0; s < NS; ++s) {
                acc[s][2 * q]     = ffma2(dm[s], w2.x, acc[s][2 * q]);
                acc[s][2 * q + 1] = ffma2(dm[s], w2.y, acc[s][2 * q + 1]);
            }
        }
    }
    #pragma unroll
    for (int k = 0; k < NP; ++k)
        #pragma unroll
        for (int s = 0; s < NS; ++s)
            unpack2(acc[s][k], v[s][2 * k], v[s][2 * k + 1]);
}

__device__ __forceinline__ void kerr16(float* v, const float* __restrict__ kp) {
    #pragma unroll
    for (int m = 0; m < 16; ++m) {
        float x = v[m], p = v[m + 16];
        float ang = kp[m] * (x * x + p * p);
        float s, c;
        __sincosf(ang, &s, &c);
        v[m]      = fmaf(c, x,  s * p);
        v[m + 16] = fmaf(c, p, -s * x);
    }
}

// ---------------------------------------------------------------------------
// Main kernel: SPT samples per thread; state in registers; weights in SMEM.
// __launch_bounds__(TPB, 3): cap regs so 3 CTAs (12 warps) are truly resident
// -- R6/R7 both silently ran at 2 CTAs (reg-alloc granularity), starving issue.
// ---------------------------------------------------------------------------
__global__ void __launch_bounds__(TPB, 3) qnet_main(
    const float* __restrict__ batch,
    const float* __restrict__ act_p,      // (5, 16)
    const float* __restrict__ last_act,   // (16,)
    float* __restrict__ out,
    int n_samples)
{
    __shared__ __align__(16) float sW[N_LAYERS - 1][32][32];  // layers 0..4: 20 KB
    __shared__ __align__(16) float sWc[32][20];               // layer 5 compact
    __shared__ float sd[N_LAYERS - 1][32];
    __shared__ float sdc[20];
    __shared__ float sk[N_LAYERS][16];

    int tid = threadIdx.x;
    {
        const float4* src = reinterpret_cast<const float4*>(g_W);
        float4* dst = reinterpret_cast<float4*>(&sW[0][0][0]);
        for (int idx = tid; idx < (N_LAYERS - 1) * 32 * 32 / 4; idx += TPB) dst[idx] = src[idx];
        const float4* srcc = reinterpret_cast<const float4*>(&g_Wc[0][0]);
        float4* dstc = reinterpret_cast<float4*>(&sWc[0][0]);
        for (int idx = tid; idx < 32 * 20 / 4; idx += TPB) dstc[idx] = srcc[idx];
        for (int idx = tid; idx < (N_LAYERS - 1) * 32; idx += TPB)
            (&sd[0][0])[idx] = (&g_d[0][0])[idx];
        if (tid < 20) sdc[tid] = g_dc[tid];
        if (tid < 80)       (&sk[0][0])[tid] = act_p[tid];
        else if (tid < 96)  (&sk[0][0])[tid] = last_act[tid - 80];
    }
    __syncthreads();

    int s0 = blockIdx.x * (TPB * SPT) + tid;          // sample of slot 0

    float v[SPT][32];
    #pragma unroll
    for (int s = 0; s < SPT; ++s) {
        int sid = s0 + s * TPB;                       // coalesced within warp
        const float4* br = reinterpret_cast<const float4*>(batch + (size_t)sid * 16);
        #pragma unroll
        for (int q = 0; q < 4; ++q) {
            float4 t = (sid < n_samples) ? br[q] : make_float4(0.f, 0.f, 0.f, 0.f);
            v[s][4 * q] = t.x; v[s][4 * q + 1] = t.y;
            v[s][4 * q + 2] = t.z; v[s][4 * q + 3] = t.w;
        }
        #pragma unroll
        for (int m = 16; m < 32; ++m) v[s][m] = 0.f;
    }

    // layer 0: inputs 16..31 are zero -> only 16 i-steps
    linearN<SPT, 16, 16, 32>(v, &sW[0][0][0], &sd[0][0]);
    #pragma unroll
    for (int s = 0; s < SPT; ++s) kerr16(v[s], &sk[0][0]);

    #pragma unroll 1
    for (int l = 1; l < N_LAYERS - 1; ++l) {
        linearN<SPT, 32, 16, 32>(v, &sW[l][0][0], &sd[l][0]);
        #pragma unroll
        for (int s = 0; s < SPT; ++s) kerr16(v[s], &sk[l][0]);
    }

    // last layer: only outputs x0..x9 (cols 0..9) and p0..p9 (cols 10..19)
    linearN<SPT, 32, 10, 20>(v, &sWc[0][0], sdc);

    #pragma unroll
    for (int s = 0; s < SPT; ++s) {
        int sid = s0 + s * TPB;
        float o10[OUT_COLS];
        #pragma unroll
        for (int m = 0; m < OUT_COLS; ++m) {
            float ka = sk[N_LAYERS - 1][m];
            float x = v[s][m], p = v[s][10 + m];
            float ang = ka * (x * x + p * p);
            float sn, cs;
            __sincosf(ang, &sn, &cs);
            o10[m] = fmaf(cs, x, sn * p);
        }
        if (sid < n_samples) {
            float2* orow = reinterpret_cast<float2*>(out + (size_t)sid * OUT_COLS);
            #pragma unroll
            for (int m = 0; m < 5; ++m) orow[m] = make_float2(o10[2 * m], o10[2 * m + 1]);
        }
    }
}

// ---------------------------------------------------------------------------
extern "C" void kernel_launch(void* const* d_in, const int* in_sizes, int n_in,
                              void* d_out, int out_size) {
    const float* batch    = (const float*)d_in[0];   // (B, 16)
    const float* lin      = (const float*)d_in[1];   // (6, 528)
    const float* act_p    = (const float*)d_in[2];   // (5, 16)
    const float* last_act = (const float*)d_in[3];   // (16,)
    float* out = (float*)d_out;

    int n_samples = in_sizes[0] / N_MODES;
    int blocks = (n_samples + TPB * SPT - 1) / (TPB * SPT);

    setup_kernel<<<1, 1024>>>(lin);
    qnet_main<<<blocks, TPB>>>(batch, act_p, last_act, out, n_samples);
}